// round 11
// baseline (speedup 1.0000x reference)
#include <cuda_runtime.h>
#include <cuda_bf16.h>
#include <cuda_fp16.h>
#include <mma.h>
#include <cstdint>

using namespace nvcuda;

#define NN 50000
#define NE 800000
#define D 128
#define NB 148
#define NT 512
#define GS (NB * NT)
#define NWARPS (NT / 32)             // 16
#define CHUNK ((NN + NB - 1) / NB)   // 338
#define NTILES ((NN + 127) / 128)    // 391
#define LDA 136                       // bf16 smem leading dim (conflict-free)
#define LDS_ 132                      // f32 staging leading dim
#define WSZ (128 * 136)               // one split-W plane (elements)

// smem byte offsets (within 1024-aligned base)
#define O_WLH 0
#define O_WLL 34816
#define O_WRH 69632
#define O_WRL 104448
#define O_AHI 139264
#define O_ALO 174080
#define SMEM_BYTES (208896 + 1024)

typedef unsigned long long u64;

// -------- device scratch --------
__device__ unsigned g_gen = 0;
__device__ unsigned g_arrive = 0;
__device__ int   g_cnt[NN];
__device__ int   g_off[NN + 1];
__device__ int   g_pos[NN];
__device__ int   g_srcs[NE];
__device__ int   g_bsum[NB];
__device__ float g_ps[NB * D];
__device__ float g_ps2[NB * D];
// pre-split weights (6 matrices, ld=136; padding stays zero-init)
__device__ __nv_bfloat16 g_wh[6 * WSZ];
__device__ __nv_bfloat16 g_wl[6 * WSZ];
// split-bf16 + fp16 feature buffers (ld = 128)
__device__ __nv_bfloat16 g_xh[NN * D];
__device__ __nv_bfloat16 g_xl[NN * D];
__device__ __half        g_x16[NN * D];
__device__ __nv_bfloat16 g_mh[NN * D];
__device__ __nv_bfloat16 g_ml[NN * D];
__device__ __nv_bfloat16 g_h0h[NN * D];
__device__ __nv_bfloat16 g_h0l[NN * D];
__device__ __half        g_h016[NN * D];
__device__ __nv_bfloat16 g_h1h[NN * D];
__device__ __nv_bfloat16 g_h1l[NN * D];
__device__ __half        g_h116[NN * D];

// -------- helpers --------
__device__ __forceinline__ uint32_t cvt2(float lo, float hi) {
    uint32_t r;
    asm("cvt.rn.bf16x2.f32 %0, %1, %2;" : "=r"(r) : "f"(hi), "f"(lo));
    return r;
}
__device__ __forceinline__ void split4(float4 v, uint2& h, uint2& l) {
    uint32_t h0 = cvt2(v.x, v.y);
    uint32_t h1 = cvt2(v.z, v.w);
    uint32_t l0 = cvt2(v.x - __uint_as_float(h0 << 16),
                       v.y - __uint_as_float(h0 & 0xffff0000u));
    uint32_t l1 = cvt2(v.z - __uint_as_float(h1 << 16),
                       v.w - __uint_as_float(h1 & 0xffff0000u));
    h = make_uint2(h0, h1);
    l = make_uint2(l0, l1);
}
__device__ __forceinline__ uint2 half4(float4 v) {
    uint2 r;
    *(__half2*)&r.x = __floats2half2_rn(v.x, v.y);
    *(__half2*)&r.y = __floats2half2_rn(v.z, v.w);
    return r;
}
__device__ __forceinline__ float4 rec4(uint2 h, uint2 l) {
    float4 v;
    v.x = __uint_as_float(h.x << 16) + __uint_as_float(l.x << 16);
    v.y = __uint_as_float(h.x & 0xffff0000u) + __uint_as_float(l.x & 0xffff0000u);
    v.z = __uint_as_float(h.y << 16) + __uint_as_float(l.y << 16);
    v.w = __uint_as_float(h.y & 0xffff0000u) + __uint_as_float(l.y & 0xffff0000u);
    return v;
}

// -------- grid-wide software barrier --------
__device__ __forceinline__ void gbar() {
    __syncthreads();
    if (threadIdx.x == 0) {
        __threadfence();
        unsigned gen = atomicAdd(&g_gen, 0u);
        unsigned arrived = atomicAdd(&g_arrive, 1u) + 1u;
        if (arrived == NB) {
            atomicExch(&g_arrive, 0u);
            __threadfence();
            atomicAdd(&g_gen, 1u);
        } else {
            while (atomicAdd(&g_gen, 0u) == gen) { __nanosleep(128); }
        }
        __threadfence();
    }
    __syncthreads();
}

// -------- mean aggregation: fp16 gather, split-bf16 mean output --------
__device__ __forceinline__ void agg_phase(const __half* __restrict__ h16) {
    const int lane = threadIdx.x & 31;
    const int warp = threadIdx.x >> 5;
    const int gw0 = blockIdx.x * NWARPS + warp;
    for (int n = gw0; n < NN; n += NB * NWARPS) {
        int beg = g_off[n];
        int end = g_off[n + 1];
        float4 a0 = make_float4(0.f, 0.f, 0.f, 0.f);
        float4 a1 = make_float4(0.f, 0.f, 0.f, 0.f);
        int i = beg;
        for (; i + 7 < end; i += 8) {
            int s0 = __ldg(&g_srcs[i]);
            int s1 = __ldg(&g_srcs[i + 1]);
            int s2 = __ldg(&g_srcs[i + 2]);
            int s3 = __ldg(&g_srcs[i + 3]);
            int s4 = __ldg(&g_srcs[i + 4]);
            int s5 = __ldg(&g_srcs[i + 5]);
            int s6 = __ldg(&g_srcs[i + 6]);
            int s7 = __ldg(&g_srcs[i + 7]);
            uint2 u0 = __ldg((const uint2*)(h16 + (size_t)s0 * D + lane * 4));
            uint2 u1 = __ldg((const uint2*)(h16 + (size_t)s1 * D + lane * 4));
            uint2 u2 = __ldg((const uint2*)(h16 + (size_t)s2 * D + lane * 4));
            uint2 u3 = __ldg((const uint2*)(h16 + (size_t)s3 * D + lane * 4));
            uint2 u4 = __ldg((const uint2*)(h16 + (size_t)s4 * D + lane * 4));
            uint2 u5 = __ldg((const uint2*)(h16 + (size_t)s5 * D + lane * 4));
            uint2 u6 = __ldg((const uint2*)(h16 + (size_t)s6 * D + lane * 4));
            uint2 u7 = __ldg((const uint2*)(h16 + (size_t)s7 * D + lane * 4));
#define ACC(acc, u) do { \
            float2 p = __half22float2(*(const __half2*)&(u).x); \
            float2 q = __half22float2(*(const __half2*)&(u).y); \
            (acc).x += p.x; (acc).y += p.y; (acc).z += q.x; (acc).w += q.y; } while (0)
            ACC(a0, u0); ACC(a0, u1); ACC(a0, u2); ACC(a0, u3);
            ACC(a1, u4); ACC(a1, u5); ACC(a1, u6); ACC(a1, u7);
        }
        for (; i < end; i++) {
            int s0 = __ldg(&g_srcs[i]);
            uint2 u0 = __ldg((const uint2*)(h16 + (size_t)s0 * D + lane * 4));
            ACC(a0, u0);
        }
#undef ACC
        float inv = 1.0f / fmaxf((float)(end - beg), 1.0f);
        float4 r;
        r.x = (a0.x + a1.x) * inv;
        r.y = (a0.y + a1.y) * inv;
        r.z = (a0.z + a1.z) * inv;
        r.w = (a0.w + a1.w) * inv;
        uint2 hh, ll;
        split4(r, hh, ll);
        *(uint2*)(g_mh + (size_t)n * D + lane * 4) = hh;
        *(uint2*)(g_ml + (size_t)n * D + lane * 4) = ll;
    }
}

// -------- A-tile register prefetch / STS --------
__device__ __forceinline__ void pf_load(uint4* pf,
                                        const __nv_bfloat16* __restrict__ Ah,
                                        const __nv_bfloat16* __restrict__ Al,
                                        int row0) {
#pragma unroll
    for (int it = 0; it < 8; it++) {
        int idx = threadIdx.x + it * NT;   // 0..4095
        int plane = idx >> 11;
        int rem = idx & 2047;
        int r = rem >> 4, g = rem & 15;
        int row = min(row0 + r, NN - 1);
        const __nv_bfloat16* src = plane ? Al : Ah;
        pf[it] = __ldg((const uint4*)(src + (size_t)row * D + g * 8));
    }
}
__device__ __forceinline__ void pf_store(const uint4* pf,
                                         __nv_bfloat16* ahi, __nv_bfloat16* alo) {
#pragma unroll
    for (int it = 0; it < 8; it++) {
        int idx = threadIdx.x + it * NT;
        int plane = idx >> 11;
        int rem = idx & 2047;
        int r = rem >> 4, g = rem & 15;
        __nv_bfloat16* dst = plane ? alo : ahi;
        *(uint4*)(dst + r * LDA + g * 8) = pf[it];
    }
}

// -------- MMA over one phase (3-product split-bf16) --------
__device__ __forceinline__ void mma_phase(
    wmma::fragment<wmma::accumulator, 16, 16, 16, float> fc[2][2],
    const __nv_bfloat16* ahi, const __nv_bfloat16* alo,
    const __nv_bfloat16* wh, const __nv_bfloat16* wl,
    int wr_, int wc_) {
#pragma unroll
    for (int ks = 0; ks < 8; ks++) {
        wmma::fragment<wmma::matrix_a, 16, 16, 16, __nv_bfloat16,
                       wmma::row_major> fa_hi[2], fa_lo[2];
        wmma::fragment<wmma::matrix_b, 16, 16, 16, __nv_bfloat16,
                       wmma::col_major> fb_hi[2], fb_lo[2];
#pragma unroll
        for (int i = 0; i < 2; i++) {
            const int r = wr_ * 32 + i * 16;
            wmma::load_matrix_sync(fa_hi[i], ahi + r * LDA + ks * 16, LDA);
            wmma::load_matrix_sync(fa_lo[i], alo + r * LDA + ks * 16, LDA);
        }
#pragma unroll
        for (int j = 0; j < 2; j++) {
            const int c = wc_ * 32 + j * 16;
            wmma::load_matrix_sync(fb_hi[j], wh + c * LDA + ks * 16, LDA);
            wmma::load_matrix_sync(fb_lo[j], wl + c * LDA + ks * 16, LDA);
        }
#pragma unroll
        for (int i = 0; i < 2; i++)
#pragma unroll
            for (int j = 0; j < 2; j++) {
                wmma::mma_sync(fc[i][j], fa_hi[i], fb_hi[j], fc[i][j]);
                wmma::mma_sync(fc[i][j], fa_hi[i], fb_lo[j], fc[i][j]);
                wmma::mma_sync(fc[i][j], fa_lo[i], fb_hi[j], fc[i][j]);
            }
    }
}

// -------- pipelined tensor-core fused dual GEMM --------
// MODE 0: relu -> (oh,ol,o16). MODE 1: -> (oh,ol) + BN partials. MODE 2: fp32 outf.
template <int MODE>
__device__ __forceinline__ void gemm_wmma(
    const __nv_bfloat16* __restrict__ a0h, const __nv_bfloat16* __restrict__ a0l,
    const __nv_bfloat16* __restrict__ a1h, const __nv_bfloat16* __restrict__ a1l,
    int wml, int wmr,                  // weight matrix indices into g_wh/g_wl
    const float* __restrict__ bias,
    float* __restrict__ outf,
    __nv_bfloat16* __restrict__ oh, __nv_bfloat16* __restrict__ ol,
    __half* __restrict__ o16, char* base) {
    __nv_bfloat16* wlh = (__nv_bfloat16*)(base + O_WLH);
    __nv_bfloat16* wll = (__nv_bfloat16*)(base + O_WLL);
    __nv_bfloat16* wrh = (__nv_bfloat16*)(base + O_WRH);
    __nv_bfloat16* wrl = (__nv_bfloat16*)(base + O_WRL);
    __nv_bfloat16* ahi = (__nv_bfloat16*)(base + O_AHI);
    __nv_bfloat16* alo = (__nv_bfloat16*)(base + O_ALO);
    float* staging = (float*)(base + O_AHI);   // aliases A buffers

    const int tid = threadIdx.x;
    const int warp = tid >> 5;
    const int wr_ = warp >> 2;
    const int wc_ = warp & 3;

    // flat W copy: 4 planes x 2176 uint4 (includes zero padding)
    {
        const uint4* s0 = (const uint4*)(g_wh + wml * WSZ);
        const uint4* s1 = (const uint4*)(g_wl + wml * WSZ);
        const uint4* s2 = (const uint4*)(g_wh + wmr * WSZ);
        const uint4* s3 = (const uint4*)(g_wl + wmr * WSZ);
        uint4* d0 = (uint4*)wlh; uint4* d1 = (uint4*)wll;
        uint4* d2 = (uint4*)wrh; uint4* d3 = (uint4*)wrl;
        for (int i = tid; i < 2176; i += NT) {
            d0[i] = __ldg(s0 + i);
            d1[i] = __ldg(s1 + i);
            d2[i] = __ldg(s2 + i);
            d3[i] = __ldg(s3 + i);
        }
    }

    float bn_s[4] = {0.f, 0.f, 0.f, 0.f};
    float bn_s2[4] = {0.f, 0.f, 0.f, 0.f};

    uint4 pf[8];
    pf_load(pf, a0h, a0l, blockIdx.x * 128);   // (t0, ph0)
    __syncthreads();                           // W ready

    for (int t = blockIdx.x; t < NTILES; t += NB) {
        const int row0 = t * 128;
        wmma::fragment<wmma::accumulator, 16, 16, 16, float> fc[2][2];
#pragma unroll
        for (int i = 0; i < 2; i++)
#pragma unroll
            for (int j = 0; j < 2; j++) wmma::fill_fragment(fc[i][j], 0.f);

        // ---- phase 0 ----
        pf_store(pf, ahi, alo);
        __syncthreads();
        pf_load(pf, a1h, a1l, row0);            // prefetch (t, ph1)
        mma_phase(fc, ahi, alo, wlh, wll, wr_, wc_);
        __syncthreads();
        // ---- phase 1 ----
        pf_store(pf, ahi, alo);
        __syncthreads();
        pf_load(pf, a0h, a0l, (t + NB) * 128);  // prefetch (t+NB, ph0); clamped
        mma_phase(fc, ahi, alo, wrh, wrl, wr_, wc_);
        __syncthreads();

        // ---- stage accumulators (staging aliases A buffers) ----
#pragma unroll
        for (int i = 0; i < 2; i++)
#pragma unroll
            for (int j = 0; j < 2; j++)
                wmma::store_matrix_sync(
                    staging + (wr_ * 32 + i * 16) * LDS_ + wc_ * 32 + j * 16,
                    fc[i][j], LDS_, wmma::mem_row_major);
        __syncthreads();

        // ---- epilogue (cq constant per thread) ----
        const int cq = tid & 31;
        float4 b4 = *(const float4*)(bias + cq * 4);
#pragma unroll
        for (int it = 0; it < 8; it++) {
            int idx = tid + it * NT;
            int r = idx >> 5;
            int row = row0 + r;
            if (row < NN) {
                float4 v = *(const float4*)(staging + r * LDS_ + cq * 4);
                v.x += b4.x; v.y += b4.y; v.z += b4.z; v.w += b4.w;
                size_t off = (size_t)row * D + cq * 4;
                if (MODE == 0) {
                    v.x = fmaxf(v.x, 0.f); v.y = fmaxf(v.y, 0.f);
                    v.z = fmaxf(v.z, 0.f); v.w = fmaxf(v.w, 0.f);
                    uint2 hh, ll;
                    split4(v, hh, ll);
                    *(uint2*)(oh + off) = hh;
                    *(uint2*)(ol + off) = ll;
                    *(uint2*)(o16 + off) = half4(v);
                } else if (MODE == 1) {
                    bn_s[0] += v.x; bn_s[1] += v.y;
                    bn_s[2] += v.z; bn_s[3] += v.w;
                    bn_s2[0] += v.x * v.x; bn_s2[1] += v.y * v.y;
                    bn_s2[2] += v.z * v.z; bn_s2[3] += v.w * v.w;
                    uint2 hh, ll;
                    split4(v, hh, ll);
                    *(uint2*)(oh + off) = hh;
                    *(uint2*)(ol + off) = ll;
                } else {
                    *(float4*)(outf + off) = v;
                }
            }
        }
        __syncthreads();   // epilogue reads done before next tile's pf_store
    }

    if (MODE == 1) {
        // block-reduce per-column partials via staging smem
        float* bs = staging;
#pragma unroll
        for (int j = 0; j < 4; j++) {
            bs[j * NT + tid] = bn_s[j];
            bs[4 * NT + j * NT + tid] = bn_s2[j];
        }
        __syncthreads();
        if (tid < D) {
            int l = tid >> 2, j = tid & 3;
            float s = 0.f, s2 = 0.f;
#pragma unroll
            for (int w = 0; w < 16; w++) {
                s += bs[j * NT + l + w * 32];
                s2 += bs[4 * NT + j * NT + l + w * 32];
            }
            g_ps[blockIdx.x * D + tid] = s;
            g_ps2[blockIdx.x * D + tid] = s2;
        }
        __syncthreads();
    }
}

// -------- the mono-kernel --------
__global__ void __launch_bounds__(NT, 1)
mono_kernel(const float* __restrict__ x,
            const int* __restrict__ src, const int* __restrict__ dst,
            const float* __restrict__ Wl0, const float* __restrict__ bl0,
            const float* __restrict__ Wr0,
            const float* __restrict__ Wl1, const float* __restrict__ bl1,
            const float* __restrict__ Wr1,
            const float* __restrict__ Wl2, const float* __restrict__ bl2,
            const float* __restrict__ Wr2,
            const float* __restrict__ gamma, const float* __restrict__ beta,
            float* __restrict__ out) {
    extern __shared__ char smc[];
    char* base = (char*)(((uintptr_t)smc + 1023) & ~(uintptr_t)1023);
    const int tid = threadIdx.x;
    const int bid = blockIdx.x;
    const int gt = bid * NT + tid;
    const int lane = tid & 31;
    const int warp = tid >> 5;

    // ---- phase 1: histogram + split x + split all 6 W matrices ----
    for (int e = gt; e < NE; e += GS) atomicAdd(&g_cnt[dst[e]], 1);
    for (int i = gt; i < NN * 32; i += GS) {
        float4 v = __ldg((const float4*)(x + (size_t)i * 4));
        uint2 h, l;
        split4(v, h, l);
        ((uint2*)g_xh)[i] = h;
        ((uint2*)g_xl)[i] = l;
        ((uint2*)g_x16)[i] = half4(v);
    }
    {
        const float* wm[6] = {Wl0, Wr0, Wl1, Wr1, Wl2, Wr2};
        for (int i = gt; i < 6 * 4096; i += GS) {
            int m = i >> 12;
            int rem = i & 4095;
            int r = rem >> 5, kq = rem & 31;
            float4 v = __ldg((const float4*)(wm[m] + r * D + kq * 4));
            uint2 h, l;
            split4(v, h, l);
            *(uint2*)(g_wh + m * WSZ + r * LDA + kq * 4) = h;
            *(uint2*)(g_wl + m * WSZ + r * LDA + kq * 4) = l;
        }
    }
    gbar();

    // ---- phase 2: per-block chunk sums ----
    {
        __shared__ int red[NWARPS];
        int cb = bid * CHUNK;
        int v = 0;
        for (int i = tid; i < CHUNK; i += NT) {
            int idx = cb + i;
            if (idx < NN) v += g_cnt[idx];
        }
#pragma unroll
        for (int o = 16; o > 0; o >>= 1) v += __shfl_down_sync(0xffffffffu, v, o);
        if (lane == 0) red[warp] = v;
        __syncthreads();
        if (warp == 0) {
            int w = (lane < NWARPS) ? red[lane] : 0;
#pragma unroll
            for (int o = 8; o > 0; o >>= 1) w += __shfl_down_sync(0xffffffffu, w, o);
            if (lane == 0) g_bsum[bid] = w;
        }
    }
    gbar();

    // ---- phase 3: every block scans block sums locally ----
    __shared__ int s_boff;
    {
        __shared__ int sb[NB];
        if (tid < NB) sb[tid] = g_bsum[tid];
        __syncthreads();
        if (tid == 0) {
            int run = 0;
            for (int b = 0; b < NB; b++) { int v = sb[b]; sb[b] = run; run += v; }
            s_boff = sb[bid];
        }
        __syncthreads();
        if (bid == NB - 1 && tid == 0) g_off[NN] = NE;
    }

    // ---- phase 4: write offsets, reset g_cnt ----
    {
        __shared__ int wsum[NWARPS];
        int cb = bid * CHUNK;
        int idx = cb + tid;
        int v = (tid < CHUNK && idx < NN) ? g_cnt[idx] : 0;
        int inc = v;
#pragma unroll
        for (int o = 1; o < 32; o <<= 1) {
            int u = __shfl_up_sync(0xffffffffu, inc, o);
            if (lane >= o) inc += u;
        }
        if (lane == 31) wsum[warp] = inc;
        __syncthreads();
        if (warp == 0) {
            int w = (lane < NWARPS) ? wsum[lane] : 0;
            int wi = w;
#pragma unroll
            for (int o = 1; o < NWARPS; o <<= 1) {
                int u = __shfl_up_sync(0xffffffffu, wi, o);
                if (lane >= o) wi += u;
            }
            if (lane < NWARPS) wsum[lane] = wi - w;
        }
        __syncthreads();
        int excl = s_boff + wsum[warp] + inc - v;
        if (tid < CHUNK && idx < NN) {
            g_off[idx] = excl;
            g_pos[idx] = excl;
            g_cnt[idx] = 0;
        }
    }
    gbar();

    // ---- phase 5: scatter src by dst ----
    for (int e = gt; e < NE; e += GS) {
        int p = atomicAdd(&g_pos[dst[e]], 1);
        g_srcs[p] = src[e];
    }
    gbar();

    // ---- layer 0 ----
    agg_phase(g_x16);
    gbar();
    gemm_wmma<0>(g_mh, g_ml, g_xh, g_xl, 0, 1, bl0,
                 nullptr, g_h0h, g_h0l, g_h016, base);
    gbar();

    // ---- layer 1 (BN partials fused into epilogue) ----
    agg_phase(g_h016);
    gbar();
    gemm_wmma<1>(g_mh, g_ml, g_h0h, g_h0l, 2, 3, bl1,
                 nullptr, g_h1h, g_h1l, nullptr, base);
    gbar();

    // ---- batchnorm finalize (replicated) + apply + relu ----
    {
        __shared__ float s_scale[D], s_shift[D];
        __shared__ float r1[NT], r2[NT];
        int col = tid & 127;
        int part = tid >> 7;  // 0..3
        float s = 0.f, s2 = 0.f;
        for (int b = part; b < NB; b += 4) {
            s += g_ps[b * D + col];
            s2 += g_ps2[b * D + col];
        }
        r1[tid] = s; r2[tid] = s2;
        __syncthreads();
        if (part == 0) {
            double S = (double)r1[col] + (double)r1[col + 128] +
                       (double)r1[col + 256] + (double)r1[col + 384];
            double S2 = (double)r2[col] + (double)r2[col + 128] +
                        (double)r2[col + 256] + (double)r2[col + 384];
            double mu = S / (double)NN;
            double var = S2 / (double)NN - mu * mu;
            float inv = rsqrtf((float)var + 1e-5f);
            float sc = inv * gamma[col];
            s_scale[col] = sc;
            s_shift[col] = beta[col] - (float)mu * sc;
        }
        __syncthreads();
        for (int i = gt; i < NN * 32; i += GS) {
            uint2 hh = ((const uint2*)g_h1h)[i];
            uint2 ll = ((const uint2*)g_h1l)[i];
            float4 v = rec4(hh, ll);
            int c = (i & 31) * 4;
            v.x = fmaxf(fmaf(v.x, s_scale[c + 0], s_shift[c + 0]), 0.f);
            v.y = fmaxf(fmaf(v.y, s_scale[c + 1], s_shift[c + 1]), 0.f);
            v.z = fmaxf(fmaf(v.z, s_scale[c + 2], s_shift[c + 2]), 0.f);
            v.w = fmaxf(fmaf(v.w, s_scale[c + 3], s_shift[c + 3]), 0.f);
            uint2 nh, nl;
            split4(v, nh, nl);
            ((uint2*)g_h1h)[i] = nh;
            ((uint2*)g_h1l)[i] = nl;
            ((uint2*)g_h116)[i] = half4(v);
        }
    }
    gbar();

    // ---- layer 2 ----
    agg_phase(g_h116);
    gbar();
    gemm_wmma<2>(g_mh, g_ml, g_h1h, g_h1l, 4, 5, bl2,
                 out, nullptr, nullptr, nullptr, base);
}

// -------- launch --------
extern "C" void kernel_launch(void* const* d_in, const int* in_sizes, int n_in,
                              void* d_out, int out_size) {
    const float* x     = (const float*)d_in[0];
    const int*   ei    = (const int*)d_in[1];
    const float* Wl0   = (const float*)d_in[2];
    const float* bl0   = (const float*)d_in[3];
    const float* Wr0   = (const float*)d_in[4];
    const float* Wl1   = (const float*)d_in[5];
    const float* bl1   = (const float*)d_in[6];
    const float* Wr1   = (const float*)d_in[7];
    const float* Wl2   = (const float*)d_in[8];
    const float* bl2   = (const float*)d_in[9];
    const float* Wr2   = (const float*)d_in[10];
    const float* gamma = (const float*)d_in[11];
    const float* beta  = (const float*)d_in[12];
    float* out = (float*)d_out;

    const int* srcp = ei;
    const int* dstp = ei + NE;

    static bool attr_set = false;
    if (!attr_set) {
        cudaFuncSetAttribute(mono_kernel,
                             cudaFuncAttributeMaxDynamicSharedMemorySize, SMEM_BYTES);
        attr_set = true;
    }

    mono_kernel<<<NB, NT, SMEM_BYTES>>>(x, srcp, dstp,
                                        Wl0, bl0, Wr0,
                                        Wl1, bl1, Wr1,
                                        Wl2, bl2, Wr2,
                                        gamma, beta, out);
}